// round 2
// baseline (speedup 1.0000x reference)
#include <cuda_runtime.h>
#include <math.h>
#include <stdint.h>

#define NN 50000
#define NE 800000
#define NEF (NE + NN)
#define NG 128
#define ED 16

// ---------------- scratch (static device globals; no runtime alloc) ----------
__device__ int      d_cnt[NN];
__device__ int      d_rowptr[NN + 1];
__device__ int      d_cursor[NN];
__device__ int      d_csr_src[NEF];
__device__ int      d_csr_eid[NEF];
__device__ float    d_loop_attr[NN * ED];
__device__ float    d_xs1[(size_t)NN * 256];
__device__ float    d_h1 [(size_t)NN * 256];
__device__ float    d_xs2[(size_t)NN * 128];
__device__ float    d_ss1[NN * 4];
__device__ float    d_sd1[NN * 4];
__device__ float    d_ss2[NN * 2];
__device__ float    d_sd2[NN * 2];
__device__ float    d_aew1[ED * 4];
__device__ float    d_aew2[ED * 2];
__device__ unsigned d_gpool[NG * 64];

// ---------------- init ----------------
__global__ void k_zero() {
    int i = blockIdx.x * blockDim.x + threadIdx.x;
    if (i < NN) { d_cnt[i] = 0; d_cursor[i] = 0; }
    if (i < NG * 64) d_gpool[i] = 0u;
}

// ---------------- in-degree count ----------------
__global__ void k_count(const int* __restrict__ dst) {
    int e = blockIdx.x * blockDim.x + threadIdx.x;
    if (e < NE) atomicAdd(&d_cnt[dst[e]], 1);
}

// ---------------- exclusive scan of (cnt+1), single block ----------------
__global__ void k_scan() {
    __shared__ int sh[1024];
    __shared__ int base;
    int t = threadIdx.x;
    if (t == 0) base = 0;
    __syncthreads();
    for (int s0 = 0; s0 < NN; s0 += 1024) {
        int idx = s0 + t;
        int v = (idx < NN) ? d_cnt[idx] + 1 : 0;
        sh[t] = v;
        __syncthreads();
        for (int off = 1; off < 1024; off <<= 1) {
            int tv = (t >= off) ? sh[t - off] : 0;
            __syncthreads();
            sh[t] += tv;
            __syncthreads();
        }
        if (idx < NN) d_rowptr[idx] = base + sh[t] - v;
        int tot = sh[1023];
        __syncthreads();
        if (t == 0) base += tot;
        __syncthreads();
    }
    if (t == 0) d_rowptr[NN] = base;  // == NEF
}

// ---------------- CSR fill ----------------
__global__ void k_fillcsr(const int* __restrict__ src, const int* __restrict__ dst) {
    int e = blockIdx.x * blockDim.x + threadIdx.x;
    if (e < NE) {
        int d = dst[e];
        int p = d_rowptr[d] + atomicAdd(&d_cursor[d], 1);
        d_csr_src[p] = src[e];
        d_csr_eid[p] = e;
    }
}
__global__ void k_fillself() {
    int n = blockIdx.x * blockDim.x + threadIdx.x;
    if (n < NN) {
        int p = d_rowptr[n + 1] - 1;  // last slot = self loop
        d_csr_src[p] = n;
        d_csr_eid[p] = NE + n;
    }
}

// ---------------- self-loop attr = per-dst mean of edge_attr ----------------
__global__ void k_loopattr(const float* __restrict__ ea) {
    int t = threadIdx.x;
    int n = blockIdx.x * 8 + (t >> 4);
    int k = t & 15;
    if (n >= NN) return;
    int b = d_rowptr[n];
    int e = d_rowptr[n + 1] - 1;  // exclude self slot
    float s = 0.f;
    for (int i = b; i < e; i++) {
        int eid = d_csr_eid[i];
        s += ea[(size_t)eid * 16 + k];
    }
    int c = e - b;
    float dv = (c > 0) ? (float)c : 1.0f;
    d_loop_attr[n * 16 + k] = s / dv;
}

// ---------------- edge-attn weight fold: aew[k][h] = sum_c We[k,h*64+c]*ae[h,c]
template <int H>
__global__ void k_aew(const float* __restrict__ We, const float* __restrict__ ae) {
    int i = threadIdx.x;
    if (i >= 16 * H) return;
    int k = i / H, h = i % H;
    float s = 0.f;
    #pragma unroll
    for (int c = 0; c < 64; c++) s += We[k * (H * 64) + h * 64 + c] * ae[h * 64 + c];
    float* out = (H == 4) ? d_aew1 : d_aew2;
    out[k * H + h] = s;
}

// ---------------- fp32 tiled GEMM: C[M,N] = A[M,K] @ B[K,N] ----------------
// MODE 1: A = x (arg),   K=128, N=256, C = d_xs1
// MODE 2: A = d_h1,      K=256, N=128, C = d_xs2
template <int MODE>
__global__ void __launch_bounds__(256) k_gemm(const float* __restrict__ Ain,
                                              const float* __restrict__ B) {
    constexpr int K = (MODE == 1) ? 128 : 256;
    constexpr int N = (MODE == 1) ? 256 : 128;
    const float* A = (MODE == 1) ? Ain : d_h1;
    float* C = (MODE == 1) ? d_xs1 : d_xs2;

    __shared__ float As[16][64];
    __shared__ float Bs[16][64];

    int tid = threadIdx.x;
    int row0 = blockIdx.x * 64, col0 = blockIdx.y * 64;
    int am = tid >> 2, ak = (tid & 3) << 2;
    int bk = tid >> 4, bn = (tid & 15) << 2;
    int ty = tid >> 4, tx = tid & 15;

    float acc[16];
    #pragma unroll
    for (int i = 0; i < 16; i++) acc[i] = 0.f;

    for (int k0 = 0; k0 < K; k0 += 16) {
        float4 av = make_float4(0.f, 0.f, 0.f, 0.f);
        if (row0 + am < NN)
            av = *(const float4*)(A + (size_t)(row0 + am) * K + k0 + ak);
        As[ak + 0][am] = av.x; As[ak + 1][am] = av.y;
        As[ak + 2][am] = av.z; As[ak + 3][am] = av.w;
        *(float4*)&Bs[bk][bn] = *(const float4*)(B + (size_t)(k0 + bk) * N + col0 + bn);
        __syncthreads();
        #pragma unroll
        for (int k = 0; k < 16; k++) {
            float4 a4 = *(float4*)&As[k][ty << 2];
            float4 b4 = *(float4*)&Bs[k][tx << 2];
            float ar[4] = {a4.x, a4.y, a4.z, a4.w};
            float br_[4] = {b4.x, b4.y, b4.z, b4.w};
            #pragma unroll
            for (int i = 0; i < 4; i++)
                #pragma unroll
                for (int j = 0; j < 4; j++) acc[i * 4 + j] += ar[i] * br_[j];
        }
        __syncthreads();
    }
    #pragma unroll
    for (int i = 0; i < 4; i++) {
        int r = row0 + (ty << 2) + i;
        if (r < NN) {
            float4 v = make_float4(acc[i * 4 + 0], acc[i * 4 + 1], acc[i * 4 + 2], acc[i * 4 + 3]);
            *(float4*)(C + (size_t)r * N + col0 + (tx << 2)) = v;
        }
    }
}

// ---------------- per-node attention coefficients s_src, s_dst ----------------
template <int H>
__global__ void k_attn(const float* __restrict__ asrc, const float* __restrict__ adst) {
    const float* xs = (H == 4) ? d_xs1 : d_xs2;
    float* so = (H == 4) ? d_ss1 : d_ss2;
    float* dd = (H == 4) ? d_sd1 : d_sd2;
    int i = blockIdx.x * blockDim.x + threadIdx.x;
    if (i >= NN * H) return;
    int n = i / H, h = i % H;
    const float* xp = xs + (size_t)n * (H * 64) + h * 64;
    float a = 0.f, b = 0.f;
    #pragma unroll
    for (int c = 0; c < 64; c++) {
        float v = xp[c];
        a += v * asrc[h * 64 + c];
        b += v * adst[h * 64 + c];
    }
    so[i] = a;
    dd[i] = b;
}

// ---------------- GAT aggregation: one block per destination node ------------
// H=4 (layer 1): writes d_h1 = relu(out + b1)
// H=2 (layer 2): mean over heads + b2, then ordered-uint atomicMax pool
template <int H>
__global__ void __launch_bounds__(H * 64) k_agg(const float* __restrict__ ea,
                                                const float* __restrict__ bias,
                                                const int* __restrict__ batch) {
    constexpr int T = H * 64;
    const float* xs  = (H == 4) ? d_xs1 : d_xs2;
    const float* ssr = (H == 4) ? d_ss1 : d_ss2;
    const float* sdr = (H == 4) ? d_sd1 : d_sd2;
    const float* aew = (H == 4) ? d_aew1 : d_aew2;

    __shared__ float s_aew[16 * H];
    __shared__ float s_sd[H];
    __shared__ float s_m[H];
    __shared__ float s_den[H];
    __shared__ float red[T * H];
    __shared__ float sw[T * H];
    __shared__ int   ssi[T];

    int n = blockIdx.x;
    int t = threadIdx.x;
    int h = t >> 6;
    if (t < 16 * H) s_aew[t] = aew[t];
    if (t < H) s_sd[t] = sdr[n * H + t];
    int rb = d_rowptr[n];
    int deg = d_rowptr[n + 1] - rb;
    __syncthreads();

    float sdl[H];
    #pragma unroll
    for (int hh = 0; hh < H; hh++) sdl[hh] = s_sd[hh];

    // ---- pass 1: per-head max over incident edges ----
    float mh[H];
    #pragma unroll
    for (int hh = 0; hh < H; hh++) mh[hh] = -3.0e38f;
    for (int i = t; i < deg; i += T) {
        int s = d_csr_src[rb + i];
        int eid = d_csr_eid[rb + i];
        const float* eap = (eid < NE) ? ea + (size_t)eid * 16
                                      : d_loop_attr + (size_t)(eid - NE) * 16;
        float se[H];
        #pragma unroll
        for (int hh = 0; hh < H; hh++) se[hh] = 0.f;
        #pragma unroll
        for (int k = 0; k < 16; k++) {
            float a = eap[k];
            #pragma unroll
            for (int hh = 0; hh < H; hh++) se[hh] += a * s_aew[k * H + hh];
        }
        #pragma unroll
        for (int hh = 0; hh < H; hh++) {
            float sc = ssr[s * H + hh] + sdl[hh] + se[hh];
            sc = (sc >= 0.f) ? sc : 0.2f * sc;
            mh[hh] = fmaxf(mh[hh], sc);
        }
    }
    #pragma unroll
    for (int hh = 0; hh < H; hh++) red[t * H + hh] = mh[hh];
    __syncthreads();
    for (int st = T / 2; st > 0; st >>= 1) {
        if (t < st) {
            #pragma unroll
            for (int hh = 0; hh < H; hh++)
                red[t * H + hh] = fmaxf(red[t * H + hh], red[(t + st) * H + hh]);
        }
        __syncthreads();
    }
    if (t < H) s_m[t] = red[t];
    __syncthreads();
    float ml[H];
    #pragma unroll
    for (int hh = 0; hh < H; hh++) ml[hh] = s_m[hh];

    // ---- pass 2: exp weights + weighted gather-accumulate ----
    float acc = 0.f;
    float dl[H];
    #pragma unroll
    for (int hh = 0; hh < H; hh++) dl[hh] = 0.f;
    for (int base = 0; base < deg; base += T) {
        int cn = min(T, deg - base);
        if (t < cn) {
            int i = base + t;
            int s = d_csr_src[rb + i];
            int eid = d_csr_eid[rb + i];
            const float* eap = (eid < NE) ? ea + (size_t)eid * 16
                                          : d_loop_attr + (size_t)(eid - NE) * 16;
            float se[H];
            #pragma unroll
            for (int hh = 0; hh < H; hh++) se[hh] = 0.f;
            #pragma unroll
            for (int k = 0; k < 16; k++) {
                float a = eap[k];
                #pragma unroll
                for (int hh = 0; hh < H; hh++) se[hh] += a * s_aew[k * H + hh];
            }
            #pragma unroll
            for (int hh = 0; hh < H; hh++) {
                float sc = ssr[s * H + hh] + sdl[hh] + se[hh];
                sc = (sc >= 0.f) ? sc : 0.2f * sc;
                float w = __expf(sc - ml[hh]);
                sw[t * H + hh] = w;
                dl[hh] += w;
            }
            ssi[t] = s;
        }
        __syncthreads();
        for (int i = 0; i < cn; i++) {
            float w = sw[i * H + h];
            acc += w * xs[(size_t)ssi[i] * T + t];
        }
        __syncthreads();
    }
    #pragma unroll
    for (int hh = 0; hh < H; hh++) red[t * H + hh] = dl[hh];
    __syncthreads();
    for (int st = T / 2; st > 0; st >>= 1) {
        if (t < st) {
            #pragma unroll
            for (int hh = 0; hh < H; hh++)
                red[t * H + hh] += red[(t + st) * H + hh];
        }
        __syncthreads();
    }
    if (t < H) s_den[t] = red[t];
    __syncthreads();

    float o = acc / (s_den[h] + 1e-16f);
    if (H == 4) {
        o += bias[t];
        d_h1[(size_t)n * T + t] = fmaxf(o, 0.f);
    } else {
        red[t] = o;
        __syncthreads();
        if (t < 64) {
            float v = 0.5f * (red[t] + red[t + 64]) + bias[t];
            unsigned b = __float_as_uint(v);
            unsigned u = (b & 0x80000000u) ? ~b : (b | 0x80000000u);
            atomicMax(&d_gpool[batch[n] * 64 + t], u);
        }
    }
}

// ---------------- readout: out[g] = max-pooled(h2) @ Wr + br ----------------
__global__ void k_readout(const float* __restrict__ Wr, const float* __restrict__ br,
                          float* __restrict__ out) {
    __shared__ float r[64];
    int g = blockIdx.x, c = threadIdx.x;
    unsigned u = d_gpool[g * 64 + c];
    unsigned b = (u & 0x80000000u) ? (u ^ 0x80000000u) : ~u;
    float f = __uint_as_float(b);
    r[c] = f * Wr[c];
    __syncthreads();
    for (int st = 32; st > 0; st >>= 1) {
        if (c < st) r[c] += r[c + st];
        __syncthreads();
    }
    if (c == 0) out[g] = r[0] + br[0];
}

// ---------------- launch ----------------
extern "C" void kernel_launch(void* const* d_in, const int* in_sizes, int n_in,
                              void* d_out, int out_size) {
    const float* x    = (const float*)d_in[0];
    const float* ea   = (const float*)d_in[1];
    const int*   ei   = (const int*)  d_in[2];
    const int*   batch= (const int*)  d_in[3];
    const float* W1   = (const float*)d_in[4];
    const float* as1  = (const float*)d_in[5];
    const float* ad1  = (const float*)d_in[6];
    const float* We1  = (const float*)d_in[7];
    const float* ae1  = (const float*)d_in[8];
    const float* b1   = (const float*)d_in[9];
    const float* W2   = (const float*)d_in[10];
    const float* as2  = (const float*)d_in[11];
    const float* ad2  = (const float*)d_in[12];
    const float* We2  = (const float*)d_in[13];
    const float* ae2  = (const float*)d_in[14];
    const float* b2   = (const float*)d_in[15];
    const float* Wr   = (const float*)d_in[16];
    const float* br   = (const float*)d_in[17];
    float* out = (float*)d_out;

    const int* srcp = ei;
    const int* dstp = ei + NE;

    k_zero<<<(NN + 255) / 256, 256>>>();
    k_count<<<(NE + 255) / 256, 256>>>(dstp);
    k_scan<<<1, 1024>>>();
    k_fillcsr<<<(NE + 255) / 256, 256>>>(srcp, dstp);
    k_fillself<<<(NN + 255) / 256, 256>>>();
    k_loopattr<<<(NN + 7) / 8, 128>>>(ea);
    k_aew<4><<<1, 64>>>(We1, ae1);
    k_aew<2><<<1, 32>>>(We2, ae2);

    k_gemm<1><<<dim3((NN + 63) / 64, 4), 256>>>(x, W1);
    k_attn<4><<<(NN * 4 + 127) / 128, 128>>>(as1, ad1);
    k_agg<4><<<NN, 256>>>(ea, b1, batch);

    k_gemm<2><<<dim3((NN + 63) / 64, 2), 256>>>(x /*unused*/, W2);
    k_attn<2><<<(NN * 2 + 127) / 128, 128>>>(as2, ad2);
    k_agg<2><<<NN, 128>>>(ea, b2, batch);

    k_readout<<<NG, 64>>>(Wr, br, out);
}

// round 6
// speedup vs baseline: 2.2648x; 2.2648x over previous
#include <cuda_runtime.h>
#include <math.h>
#include <stdint.h>

#define NN 50000
#define NE 800000
#define NEF (NE + NN)
#define NG 128
#define ED 16

// ---------------- scratch (static device globals; no runtime alloc) ----------
__device__ int      d_cnt[NN];
__device__ int      d_rowptr[NN + 1];
__device__ int      d_cursor[NN];
__device__ int      d_csr_src[NEF];
__device__ int      d_csr_eid[NEF];
__device__ float    d_xs1[(size_t)NN * 256];
__device__ float    d_h1 [(size_t)NN * 256];
__device__ float    d_xs2[(size_t)NN * 128];
__device__ float4   d_ss1[NN];
__device__ float4   d_sd1[NN];
__device__ float2   d_ss2[NN];
__device__ float2   d_sd2[NN];
__device__ float4   d_se1[NEF];     // per-edge (incl. self-loop) attn score, layer 1
__device__ float2   d_se2[NEF];     // layer 2
__device__ float    d_sum1[NN * 4]; // per-dst sum of se (layer1) for self-loop mean
__device__ float    d_sum2[NN * 2];
__device__ float    d_aew1[ED * 4];
__device__ float    d_aew2[ED * 2];
__device__ unsigned d_gpool[NG * 64];

// ---------------- init ----------------
__global__ void k_zero() {
    int i = blockIdx.x * blockDim.x + threadIdx.x;
    if (i < NN) {
        d_cnt[i] = 0; d_cursor[i] = 0;
        d_sum1[i * 4 + 0] = 0.f; d_sum1[i * 4 + 1] = 0.f;
        d_sum1[i * 4 + 2] = 0.f; d_sum1[i * 4 + 3] = 0.f;
        d_sum2[i * 2 + 0] = 0.f; d_sum2[i * 2 + 1] = 0.f;
    }
    if (i < NG * 64) d_gpool[i] = 0u;
}

// ---------------- in-degree count ----------------
__global__ void k_count(const int* __restrict__ dst) {
    int e = blockIdx.x * blockDim.x + threadIdx.x;
    if (e < NE) atomicAdd(&d_cnt[dst[e]], 1);
}

// ---------------- exclusive scan of (cnt+1), single block ----------------
__global__ void k_scan() {
    __shared__ int sh[1024];
    __shared__ int base;
    int t = threadIdx.x;
    if (t == 0) base = 0;
    __syncthreads();
    for (int s0 = 0; s0 < NN; s0 += 1024) {
        int idx = s0 + t;
        int v = (idx < NN) ? d_cnt[idx] + 1 : 0;
        sh[t] = v;
        __syncthreads();
        for (int off = 1; off < 1024; off <<= 1) {
            int tv = (t >= off) ? sh[t - off] : 0;
            __syncthreads();
            sh[t] += tv;
            __syncthreads();
        }
        if (idx < NN) d_rowptr[idx] = base + sh[t] - v;
        int tot = sh[1023];
        __syncthreads();
        if (t == 0) base += tot;
        __syncthreads();
    }
    if (t == 0) d_rowptr[NN] = base;  // == NEF
}

// ---------------- CSR fill ----------------
__global__ void k_fillcsr(const int* __restrict__ src, const int* __restrict__ dst) {
    int e = blockIdx.x * blockDim.x + threadIdx.x;
    if (e < NE) {
        int d = dst[e];
        int p = d_rowptr[d] + atomicAdd(&d_cursor[d], 1);
        d_csr_src[p] = src[e];
        d_csr_eid[p] = e;
    }
}
__global__ void k_fillself() {
    int n = blockIdx.x * blockDim.x + threadIdx.x;
    if (n < NN) {
        int p = d_rowptr[n + 1] - 1;  // last slot = self loop
        d_csr_src[p] = n;
        d_csr_eid[p] = NE + n;
    }
}

// ---------------- edge-attn weight fold: aew[k][h] = sum_c We[k,h*64+c]*ae[h,c]
template <int H>
__global__ void k_aew(const float* __restrict__ We, const float* __restrict__ ae) {
    int i = threadIdx.x;
    if (i >= 16 * H) return;
    int k = i / H, h = i % H;
    float s = 0.f;
    #pragma unroll
    for (int c = 0; c < 64; c++) s += We[k * (H * 64) + h * 64 + c] * ae[h * 64 + c];
    float* out = (H == 4) ? d_aew1 : d_aew2;
    out[k * H + h] = s;
}

// ---------------- per-edge score parts for BOTH layers in one pass -----------
// se1[e,h] = aew1 . ea[e] (4 heads), se2[e,h] = aew2 . ea[e] (2 heads).
// Also accumulates per-dst sums for the self-loop (mean) scores.
__global__ void __launch_bounds__(256) k_edgescore(const float* __restrict__ ea,
                                                   const int* __restrict__ dst) {
    __shared__ float s_aew1[16 * 4];
    __shared__ float s_aew2[16 * 2];
    int t = threadIdx.x;
    if (t < 64) s_aew1[t] = d_aew1[t];
    else if (t < 96) s_aew2[t - 64] = d_aew2[t - 64];
    __syncthreads();
    int e = blockIdx.x * 256 + t;
    if (e >= NE) return;
    const float4* ep = (const float4*)(ea + (size_t)e * 16);
    float4 v0 = ep[0], v1 = ep[1], v2 = ep[2], v3 = ep[3];
    float ev[16] = {v0.x, v0.y, v0.z, v0.w, v1.x, v1.y, v1.z, v1.w,
                    v2.x, v2.y, v2.z, v2.w, v3.x, v3.y, v3.z, v3.w};
    float se1[4] = {0.f, 0.f, 0.f, 0.f};
    float se2[2] = {0.f, 0.f};
    #pragma unroll
    for (int k = 0; k < 16; k++) {
        float a = ev[k];
        #pragma unroll
        for (int h = 0; h < 4; h++) se1[h] += a * s_aew1[k * 4 + h];
        #pragma unroll
        for (int h = 0; h < 2; h++) se2[h] += a * s_aew2[k * 2 + h];
    }
    int d = dst[e];
    d_se1[e] = make_float4(se1[0], se1[1], se1[2], se1[3]);
    d_se2[e] = make_float2(se2[0], se2[1]);
    #pragma unroll
    for (int h = 0; h < 4; h++) atomicAdd(&d_sum1[d * 4 + h], se1[h]);
    #pragma unroll
    for (int h = 0; h < 2; h++) atomicAdd(&d_sum2[d * 2 + h], se2[h]);
}

// ---------------- self-loop score = mean of incident edge scores -------------
__global__ void k_loopscore() {
    int n = blockIdx.x * blockDim.x + threadIdx.x;
    if (n >= NN) return;
    int c = d_cnt[n];
    float inv = 1.0f / (float)max(c, 1);
    d_se1[NE + n] = make_float4(d_sum1[n * 4 + 0] * inv, d_sum1[n * 4 + 1] * inv,
                                d_sum1[n * 4 + 2] * inv, d_sum1[n * 4 + 3] * inv);
    d_se2[NE + n] = make_float2(d_sum2[n * 2 + 0] * inv, d_sum2[n * 2 + 1] * inv);
}

// ---------------- fp32 tiled GEMM: C[M,N] = A[M,K] @ B[K,N] ----------------
// 128x64 tile, 256 threads, 8x4 per thread.
// MODE 1: A = x (arg),   K=128, N=256, C = d_xs1
// MODE 2: A = d_h1,      K=256, N=128, C = d_xs2
template <int MODE>
__global__ void __launch_bounds__(256) k_gemm(const float* __restrict__ Ain,
                                              const float* __restrict__ B) {
    constexpr int K = (MODE == 1) ? 128 : 256;
    constexpr int N = (MODE == 1) ? 256 : 128;
    const float* A = (MODE == 1) ? Ain : d_h1;
    float* C = (MODE == 1) ? d_xs1 : d_xs2;

    __shared__ float As[16][132];   // [k][m], padded
    __shared__ float Bs[16][64];    // [k][n]

    int tid = threadIdx.x;
    int row0 = blockIdx.x * 128, col0 = blockIdx.y * 64;
    int arow = tid >> 1, ak = (tid & 1) * 8;
    int brow = tid >> 4, bc = (tid & 15) * 4;
    int trow = (tid >> 4) * 8, tcol = (tid & 15) * 4;

    float acc[8][4];
    #pragma unroll
    for (int i = 0; i < 8; i++)
        #pragma unroll
        for (int j = 0; j < 4; j++) acc[i][j] = 0.f;

    for (int k0 = 0; k0 < K; k0 += 16) {
        float4 a0 = make_float4(0.f, 0.f, 0.f, 0.f);
        float4 a1 = make_float4(0.f, 0.f, 0.f, 0.f);
        if (row0 + arow < NN) {
            const float* ap = A + (size_t)(row0 + arow) * K + k0 + ak;
            a0 = *(const float4*)(ap);
            a1 = *(const float4*)(ap + 4);
        }
        As[ak + 0][arow] = a0.x; As[ak + 1][arow] = a0.y;
        As[ak + 2][arow] = a0.z; As[ak + 3][arow] = a0.w;
        As[ak + 4][arow] = a1.x; As[ak + 5][arow] = a1.y;
        As[ak + 6][arow] = a1.z; As[ak + 7][arow] = a1.w;
        *(float4*)&Bs[brow][bc] = *(const float4*)(B + (size_t)(k0 + brow) * N + col0 + bc);
        __syncthreads();
        #pragma unroll
        for (int k = 0; k < 16; k++) {
            float4 b4 = *(float4*)&Bs[k][tcol];
            float4 aa = *(float4*)&As[k][trow];
            float4 ab = *(float4*)&As[k][trow + 4];
            float ar[8] = {aa.x, aa.y, aa.z, aa.w, ab.x, ab.y, ab.z, ab.w};
            float br_[4] = {b4.x, b4.y, b4.z, b4.w};
            #pragma unroll
            for (int i = 0; i < 8; i++)
                #pragma unroll
                for (int j = 0; j < 4; j++) acc[i][j] += ar[i] * br_[j];
        }
        __syncthreads();
    }
    #pragma unroll
    for (int i = 0; i < 8; i++) {
        int r = row0 + trow + i;
        if (r < NN) {
            float4 v = make_float4(acc[i][0], acc[i][1], acc[i][2], acc[i][3]);
            *(float4*)(C + (size_t)r * N + col0 + tcol) = v;
        }
    }
}

// ---------------- per-node attention coefficients s_src, s_dst ----------------
template <int H>
__global__ void k_attn(const float* __restrict__ asrc, const float* __restrict__ adst) {
    const float* xs = (H == 4) ? d_xs1 : d_xs2;
    int i = blockIdx.x * blockDim.x + threadIdx.x;
    if (i >= NN * H) return;
    int n = i / H, h = i % H;
    const float4* xp = (const float4*)(xs + (size_t)n * (H * 64) + h * 64);
    const float4* ap = (const float4*)(asrc + h * 64);
    const float4* bp = (const float4*)(adst + h * 64);
    float a = 0.f, b = 0.f;
    #pragma unroll
    for (int c = 0; c < 16; c++) {
        float4 v = xp[c];
        float4 av = ap[c];
        float4 bv = bp[c];
        a += v.x * av.x + v.y * av.y + v.z * av.z + v.w * av.w;
        b += v.x * bv.x + v.y * bv.y + v.z * bv.z + v.w * bv.w;
    }
    float* so = (H == 4) ? (float*)d_ss1 : (float*)d_ss2;
    float* dd = (H == 4) ? (float*)d_sd1 : (float*)d_sd2;
    so[i] = a;
    dd[i] = b;
}

// ---------------- GAT aggregation: one block per destination node ------------
// Single pass, online softmax, warp-level reductions.
// H=4 (layer 1): writes d_h1 = relu(out + b1)
// H=2 (layer 2): mean over heads + b2, then ordered-uint atomicMax pool
template <int H>
__global__ void __launch_bounds__(H * 64) k_agg(const float* __restrict__ bias,
                                                const int* __restrict__ batch) {
    constexpr int T = H * 64;
    const float* xs = (H == 4) ? d_xs1 : d_xs2;

    __shared__ float s_sc[T * H];
    __shared__ int   s_src[T];
    __shared__ float s_m[H], s_den[H], s_tm[H], s_fac[H];

    int n = blockIdx.x;
    int t = threadIdx.x;
    int h = t >> 6;
    int wid = t >> 5, lane = t & 31;
    int rb = d_rowptr[n];
    int deg = d_rowptr[n + 1] - rb;

    if (t < H) { s_m[t] = -3.0e38f; s_den[t] = 0.f; }

    float sd[H];
    if (H == 4) {
        float4 v = d_sd1[n];
        sd[0] = v.x; sd[1] = v.y; sd[2] = v.z; sd[3] = v.w;
    } else {
        float2 v = d_sd2[n];
        sd[0] = v.x; sd[1] = v.y;
    }
    __syncthreads();

    float acc = 0.f;
    for (int base = 0; base < deg; base += T) {
        int cn = min(T, deg - base);
        if (t < cn) {
            int s = d_csr_src[rb + base + t];
            int eid = d_csr_eid[rb + base + t];
            float se[H], ss[H];
            if (H == 4) {
                float4 a = d_se1[eid]; float4 b = d_ss1[s];
                se[0] = a.x; se[1] = a.y; se[2] = a.z; se[3] = a.w;
                ss[0] = b.x; ss[1] = b.y; ss[2] = b.z; ss[3] = b.w;
            } else {
                float2 a = d_se2[eid]; float2 b = d_ss2[s];
                se[0] = a.x; se[1] = a.y;
                ss[0] = b.x; ss[1] = b.y;
            }
            s_src[t] = s;
            #pragma unroll
            for (int hh = 0; hh < H; hh++) {
                float sc = ss[hh] + sd[hh] + se[hh];
                sc = (sc >= 0.f) ? sc : 0.2f * sc;
                s_sc[t * H + hh] = sc;
            }
        }
        __syncthreads();
        if (wid < H) {
            float m = -3.0e38f;
            for (int i = lane; i < cn; i += 32) m = fmaxf(m, s_sc[i * H + wid]);
            #pragma unroll
            for (int o = 16; o > 0; o >>= 1)
                m = fmaxf(m, __shfl_xor_sync(0xffffffffu, m, o));
            if (lane == 0) s_tm[wid] = m;
        }
        __syncthreads();
        if (t < cn) {
            #pragma unroll
            for (int hh = 0; hh < H; hh++) {
                float nm = fmaxf(s_m[hh], s_tm[hh]);
                s_sc[t * H + hh] = __expf(s_sc[t * H + hh] - nm);
            }
        }
        __syncthreads();
        if (wid < H) {
            float ds = 0.f;
            for (int i = lane; i < cn; i += 32) ds += s_sc[i * H + wid];
            #pragma unroll
            for (int o = 16; o > 0; o >>= 1)
                ds += __shfl_xor_sync(0xffffffffu, ds, o);
            if (lane == 0) {
                float old = s_m[wid];
                float nm = fmaxf(old, s_tm[wid]);
                float f = __expf(old - nm);
                s_den[wid] = s_den[wid] * f + ds;
                s_m[wid] = nm;
                s_fac[wid] = f;
            }
        }
        __syncthreads();
        acc *= s_fac[h];
        const float* xp = xs + t;
        for (int i = 0; i < cn; i++)
            acc += s_sc[i * H + h] * xp[(size_t)s_src[i] * T];
        __syncthreads();
    }

    float o = acc / (s_den[h] + 1e-16f);
    if (H == 4) {
        o += bias[t];
        d_h1[(size_t)n * T + t] = fmaxf(o, 0.f);
    } else {
        s_sc[t] = o;
        __syncthreads();
        if (t < 64) {
            float v = 0.5f * (s_sc[t] + s_sc[t + 64]) + bias[t];
            unsigned b = __float_as_uint(v);
            unsigned u = (b & 0x80000000u) ? ~b : (b | 0x80000000u);
            atomicMax(&d_gpool[batch[n] * 64 + t], u);
        }
    }
}

// ---------------- readout: out[g] = max-pooled(h2) @ Wr + br ----------------
__global__ void k_readout(const float* __restrict__ Wr, const float* __restrict__ br,
                          float* __restrict__ out) {
    __shared__ float r[64];
    int g = blockIdx.x, c = threadIdx.x;
    unsigned u = d_gpool[g * 64 + c];
    unsigned b = (u & 0x80000000u) ? (u ^ 0x80000000u) : ~u;
    float f = __uint_as_float(b);
    r[c] = f * Wr[c];
    __syncthreads();
    for (int st = 32; st > 0; st >>= 1) {
        if (c < st) r[c] += r[c + st];
        __syncthreads();
    }
    if (c == 0) out[g] = r[0] + br[0];
}

// ---------------- launch ----------------
extern "C" void kernel_launch(void* const* d_in, const int* in_sizes, int n_in,
                              void* d_out, int out_size) {
    const float* x    = (const float*)d_in[0];
    const float* ea   = (const float*)d_in[1];
    const int*   ei   = (const int*)  d_in[2];
    const int*   batch= (const int*)  d_in[3];
    const float* W1   = (const float*)d_in[4];
    const float* as1  = (const float*)d_in[5];
    const float* ad1  = (const float*)d_in[6];
    const float* We1  = (const float*)d_in[7];
    const float* ae1  = (const float*)d_in[8];
    const float* b1   = (const float*)d_in[9];
    const float* W2   = (const float*)d_in[10];
    const float* as2  = (const float*)d_in[11];
    const float* ad2  = (const float*)d_in[12];
    const float* We2  = (const float*)d_in[13];
    const float* ae2  = (const float*)d_in[14];
    const float* b2   = (const float*)d_in[15];
    const float* Wr   = (const float*)d_in[16];
    const float* br   = (const float*)d_in[17];
    float* out = (float*)d_out;

    const int* srcp = ei;
    const int* dstp = ei + NE;

    k_zero<<<(NN + 255) / 256, 256>>>();
    k_aew<4><<<1, 64>>>(We1, ae1);
    k_aew<2><<<1, 32>>>(We2, ae2);
    k_count<<<(NE + 255) / 256, 256>>>(dstp);
    k_scan<<<1, 1024>>>();
    k_fillcsr<<<(NE + 255) / 256, 256>>>(srcp, dstp);
    k_fillself<<<(NN + 255) / 256, 256>>>();
    k_edgescore<<<(NE + 255) / 256, 256>>>(ea, dstp);
    k_loopscore<<<(NN + 255) / 256, 256>>>();

    k_gemm<1><<<dim3((NN + 127) / 128, 4), 256>>>(x, W1);
    k_attn<4><<<(NN * 4 + 127) / 128, 128>>>(as1, ad1);
    k_agg<4><<<NN, 256>>>(b1, batch);

    k_gemm<2><<<dim3((NN + 127) / 128, 2), 256>>>(x /*unused*/, W2);
    k_attn<2><<<(NN * 2 + 127) / 128, 128>>>(as2, ad2);
    k_agg<2><<<NN, 128>>>(b2, batch);

    k_readout<<<NG, 64>>>(Wr, br, out);
}